// round 6
// baseline (speedup 1.0000x reference)
#include <cuda_runtime.h>
#include <math.h>

// dims: (1,1,D=160,H=192,W=160), x fastest
#define DW 160
#define DH 192
#define DD 160
#define SLICE (DH*DW)
#define NVOX (DD*SLICE)

#define CZ 16
#define NZC (DD/CZ)            // 10
#define NSEG 6                 // x segments of 30 outputs (covers 180 >= 160)
#define WPB 8                  // warps per block (8 consecutive y rows)
#define NTHREADS (WPB*32)
#define GYB (DH/WPB)           // 24
#define NBLOCKS (NSEG*GYB*NZC) // 1440
#define FEPS 1e-10f

__device__ float g_partial[NBLOCKS];
__device__ unsigned int g_count = 0;

// minimax atan: odd poly on [0,1], reciprocal fold for |x|>1. max err ~2e-6 rad.
__device__ __forceinline__ float fast_atanf(float x)
{
    const float ax = fabsf(x);
    const bool inv = ax > 1.0f;
    const float t = inv ? __fdividef(1.0f, ax) : ax;
    const float z = t * t;
    float p = -0.0117212f;
    p = fmaf(p, z, 0.05265332f);
    p = fmaf(p, z, -0.11643287f);
    p = fmaf(p, z, 0.19354346f);
    p = fmaf(p, z, -0.33262347f);
    p = fmaf(p, z, 0.99997726f);
    p = p * t;
    const float r = inv ? (1.5707963267948966f - p) : p;
    return copysignf(r, x);
}

__global__ __launch_bounds__(NTHREADS, 4)
void demons_kernel(const float* __restrict__ Mp,
                   const float* __restrict__ Sp,
                   const float* __restrict__ Fp,
                   float* __restrict__ out)
{
    __shared__ float warpred[WPB];
    __shared__ bool isLast;

    const int lane = threadIdx.x & 31;
    const int wid  = threadIdx.x >> 5;
    const int tid  = threadIdx.x;

    const int y     = blockIdx.y * WPB + wid;          // 0..191, every warp emits
    const int xload = blockIdx.x * 30 + lane - 1;      // -1..179
    const int zbase = blockIdx.z * CZ;
    const int bid   = blockIdx.x + NSEG * (blockIdx.y + GYB * blockIdx.z);

    const bool vx  = ((unsigned)xload < (unsigned)DW);
    const bool vym = (y > 0);
    const bool vyp = (y < DH - 1);
    const bool evalid = vx && ((unsigned)(lane - 1) < 30u);

    const int base = y * DW + (vx ? xload : 0);

    // incremental pointers (center row); rows y-1/y+1 via +/-DW immediates
    const float* pM = Mp + (zbase - 1) * SLICE + base;
    const float* pS = Sp + (zbase - 1) * SLICE + base;
    const float* pF = Fp + zbase * SLICE + base;

    // depth-2 M/S pipeline: P = slice used this iter, Q = next
    float Pm0, Pm1, Pm2, Ps0, Ps1, Ps2;
    float Qm0, Qm1, Qm2, Qs0, Qs1, Qs2;
    {
        const bool zin = (zbase - 1 >= 0);
        const bool g0 = vx && vym && zin, g1 = vx && zin, g2 = vx && vyp && zin;
        Pm0 = g0 ? __ldg(pM - DW) : 0.f;  Pm1 = g1 ? __ldg(pM) : 0.f;  Pm2 = g2 ? __ldg(pM + DW) : 0.f;
        Ps0 = g0 ? __ldg(pS - DW) : 0.f;  Ps1 = g1 ? __ldg(pS) : 0.f;  Ps2 = g2 ? __ldg(pS + DW) : 0.f;
        pM += SLICE; pS += SLICE;
        const bool h0 = vx && vym, h1 = vx, h2 = vx && vyp;
        Qm0 = h0 ? __ldg(pM - DW) : 0.f;  Qm1 = h1 ? __ldg(pM) : 0.f;  Qm2 = h2 ? __ldg(pM + DW) : 0.f;
        Qs0 = h0 ? __ldg(pS - DW) : 0.f;  Qs1 = h1 ? __ldg(pS) : 0.f;  Qs2 = h2 ? __ldg(pS + DW) : 0.f;
        pM += SLICE; pS += SLICE;
    }

    // depth-2 flow pipeline: emits j=2 (z=zbase) and j=3
    float Pfx = 0.f, Pfy = 0.f, Pfz = 0.f, Qfx = 0.f, Qfy = 0.f, Qfz = 0.f;
    if (vx) {
        Pfx = __ldg(pF); Pfy = __ldg(pF + NVOX); Pfz = __ldg(pF + 2 * NVOX);
        Qfx = __ldg(pF + SLICE); Qfy = __ldg(pF + SLICE + NVOX); Qfz = __ldg(pF + SLICE + 2 * NVOX);
    }
    pF += 2 * SLICE;

    // per-slice responses, register ring of 3 (unroll 3 -> MOVs rename away)
    float AM0, AM1, AM2, BM0, BM1, BM2, CM0, CM1, CM2, Mc1, Mc2;
    float AS0, AS1, AS2, BS0, BS1, BS2, CS0, CS1, CS2, Sc1, Sc2;
    AM0=AM1=BM0=BM1=CM0=CM1=Mc1=0.f;
    AS0=AS1=BS0=BS1=CS0=CS1=Sc1=0.f;
    float acc = 0.f;

    #pragma unroll 3
    for (int j = 0; j <= CZ + 1; ++j) {
        // consume P
        const float m0 = Pm0, m1 = Pm1, m2 = Pm2;
        const float s0 = Ps0, s1 = Ps1, s2 = Ps2;

        // rotate and issue loads for slice zbase+j+1 (used 2 iters later)
        Pm0 = Qm0; Pm1 = Qm1; Pm2 = Qm2; Ps0 = Qs0; Ps1 = Qs1; Ps2 = Qs2;
        if (j <= CZ - 1) {
            const bool zin = (zbase + j + 1 < DD);
            const bool g0 = vx && vym && zin, g1 = vx && zin, g2 = vx && vyp && zin;
            Qm0 = g0 ? __ldg(pM - DW) : 0.f;  Qm1 = g1 ? __ldg(pM) : 0.f;  Qm2 = g2 ? __ldg(pM + DW) : 0.f;
            Qs0 = g0 ? __ldg(pS - DW) : 0.f;  Qs1 = g1 ? __ldg(pS) : 0.f;  Qs2 = g2 ? __ldg(pS + DW) : 0.f;
            pM += SLICE; pS += SLICE;
        }

        // y-reduction (3 flops per image), then x via shuffles
        const float ySmM = fmaf(2.f, m1, m0 + m2);
        const float yDfM = m2 - m0;
        const float ySmS = fmaf(2.f, s1, s0 + s2);
        const float yDfS = s2 - s0;

        const float smMl = __shfl_up_sync(0xffffffffu, ySmM, 1);
        const float smMr = __shfl_down_sync(0xffffffffu, ySmM, 1);
        const float dfMl = __shfl_up_sync(0xffffffffu, yDfM, 1);
        const float dfMr = __shfl_down_sync(0xffffffffu, yDfM, 1);
        const float smSl = __shfl_up_sync(0xffffffffu, ySmS, 1);
        const float smSr = __shfl_down_sync(0xffffffffu, ySmS, 1);
        const float dfSl = __shfl_up_sync(0xffffffffu, yDfS, 1);
        const float dfSr = __shfl_down_sync(0xffffffffu, yDfS, 1);

        AM2 = smMr - smMl;                    // smooth_y x diff_x
        BM2 = fmaf(2.f, yDfM, dfMl + dfMr);   // diff_y x smooth_x
        CM2 = smMl + ySmM + smMr;             // smooth_y x box_x
        Mc2 = m1;
        AS2 = smSr - smSl;
        BS2 = fmaf(2.f, yDfS, dfSl + dfSr);
        CS2 = smSl + ySmS + smSr;
        Sc2 = s1;

        // emit voxel z = zbase + j - 2 once three slices are live
        if (j >= 2) {
            if (evalid) {
                const float Mx = AM0 + AM1 + AM2;
                const float My = BM0 + BM1 + BM2;
                const float Mz = CM2 - CM0;
                const float Sx = AS0 + AS1 + AS2;
                const float Sy = BS0 + BS1 + BS2;
                const float Sz = CS2 - CS0;

                const float Id  = Mc1 - Sc1;
                const float Id2 = fmaf(Id, Id, FEPS);
                const float dS = fmaf(Sx, Sx, fmaf(Sy, Sy, fmaf(Sz, Sz, Id2)));
                const float dM = fmaf(Mx, Mx, fmaf(My, My, fmaf(Mz, Mz, Id2)));
                const float invS = __fdividef(1.f, dS);
                const float invM = __fdividef(1.f, dM);
                const float Ux = Id * fmaf(Sx, invS, Mx * invM);
                const float Uy = Id * fmaf(Sy, invS, My * invM);
                const float Uz = Id * fmaf(Sz, invS, Mz * invM);

                const float izd = __fdividef(1.f, Uz + FEPS);
                const float dxz = fast_atanf(Ux * izd);
                const float dyz = fast_atanf(Uy * izd);

                const float ifz = __fdividef(1.f, Pfz + FEPS);
                const float fxz = fast_atanf(Pfx * ifz);
                const float fyz = fast_atanf(Pfy * ifz);

                const float e1 = fxz - dxz;
                const float e2 = fyz - dyz;
                acc = fmaf(e1, e1, acc);
                acc = fmaf(e2, e2, acc);
            }
            // rotate flow pipeline; load F for z = zbase+j (emit at j+2)
            Pfx = Qfx; Pfy = Qfy; Pfz = Qfz;
            if (j <= CZ - 1) {
                if (vx) {
                    Qfx = __ldg(pF);
                    Qfy = __ldg(pF + NVOX);
                    Qfz = __ldg(pF + 2 * NVOX);
                }
                pF += SLICE;
            }
        }

        // ring shift (renamed away under unroll 3)
        AM0 = AM1; AM1 = AM2;  BM0 = BM1; BM1 = BM2;
        CM0 = CM1; CM1 = CM2;  Mc1 = Mc2;
        AS0 = AS1; AS1 = AS2;  BS0 = BS1; BS1 = BS2;
        CS0 = CS1; CS1 = CS2;  Sc1 = Sc2;
    }

    // block reduction: warp shuffle + smem (only sync in the kernel)
    #pragma unroll
    for (int o = 16; o > 0; o >>= 1) acc += __shfl_xor_sync(0xffffffffu, acc, o);
    if (lane == 0) warpred[wid] = acc;
    __syncthreads();
    if (tid == 0) {
        float v = 0.f;
        #pragma unroll
        for (int w = 0; w < WPB; ++w) v += warpred[w];
        g_partial[bid] = v;
        __threadfence();
        const unsigned int c = atomicAdd(&g_count, 1u);
        isLast = (c == (unsigned)(NBLOCKS - 1));
    }
    __syncthreads();

    // last block reduces partials, writes scalar, resets counter
    if (isLast) {
        float s = 0.f;
        for (int i = tid; i < NBLOCKS; i += NTHREADS) s += g_partial[i];
        #pragma unroll
        for (int o = 16; o > 0; o >>= 1) s += __shfl_xor_sync(0xffffffffu, s, o);
        if (lane == 0) warpred[wid] = s;
        __syncthreads();
        if (tid == 0) {
            float t = 0.f;
            #pragma unroll
            for (int w = 0; w < WPB; ++w) t += warpred[w];
            out[0] = t / (float)NVOX;
            g_count = 0u;
        }
    }
}

extern "C" void kernel_launch(void* const* d_in, const int* in_sizes, int n_in,
                              void* d_out, int out_size)
{
    const float* Mp = (const float*)d_in[0];
    const float* Sp = (const float*)d_in[1];
    const float* Fp = (const float*)d_in[2];
    float* out = (float*)d_out;

    dim3 grid(NSEG, GYB, NZC);     // (6, 24, 10) = 1440 blocks
    dim3 block(NTHREADS, 1, 1);    // 256 threads = 8 warps
    demons_kernel<<<grid, block>>>(Mp, Sp, Fp, out);
}

// round 8
// speedup vs baseline: 1.0492x; 1.0492x over previous
#include <cuda_runtime.h>
#include <math.h>

// dims: (1,1,D=160,H=192,W=160), x fastest
#define DW 160
#define DH 192
#define DD 160
#define SLICE (DH*DW)
#define NVOX (DD*SLICE)

#define TX 32
#define TY 8
#define CZ 16
#define SMW (TX+2)
#define SMH (TY+2)
#define NTHREADS (TX*TY)
#define GXD (DW/TX)   // 5
#define GYD (DH/TY)   // 24
#define GZD (DD/CZ)   // 10
#define NBLOCKS (GXD*GYD*GZD)   // 1200
#define FEPS 1e-10f

__device__ float g_partial[NBLOCKS];
__device__ unsigned int g_count = 0;

// minimax atan: odd poly on [0,1], reciprocal fold for |x|>1. max err ~2e-6 rad.
__device__ __forceinline__ float fast_atanf(float x)
{
    const float ax = fabsf(x);
    const bool inv = ax > 1.0f;
    const float t = inv ? __fdividef(1.0f, ax) : ax;
    const float z = t * t;
    float p = -0.0117212f;
    p = fmaf(p, z, 0.05265332f);
    p = fmaf(p, z, -0.11643287f);
    p = fmaf(p, z, 0.19354346f);
    p = fmaf(p, z, -0.33262347f);
    p = fmaf(p, z, 0.99997726f);
    p = p * t;
    const float r = inv ? (1.5707963267948966f - p) : p;
    return copysignf(r, x);
}

__global__ __launch_bounds__(NTHREADS, 4)
void demons_kernel(const float* __restrict__ Mp,
                   const float* __restrict__ Sp,
                   const float* __restrict__ Fp,
                   float* __restrict__ out)
{
    __shared__ float2 sm[3][SMH][SMW];      // tri-buffer: b = j % 3 (const under unroll 3)
    __shared__ float warpred[NTHREADS / 32];
    __shared__ bool isLast;

    const int tx = threadIdx.x, ty = threadIdx.y;
    const int tid = ty * TX + tx;
    const int x = blockIdx.x * TX + tx;
    const int y = blockIdx.y * TY + ty;
    const int zbase = blockIdx.z * CZ;
    const int bid = blockIdx.x + GXD * (blockIdx.y + GYD * blockIdx.z);

    // halo mapping (z-invariant): each thread covers <=2 of 340 slots
    const int ly0 = tid / SMW, lx0 = tid - ly0 * SMW;
    const int gy0 = blockIdx.y * TY + ly0 - 1;
    const int gx0 = blockIdx.x * TX + lx0 - 1;
    const bool v0 = ((unsigned)gy0 < (unsigned)DH) && ((unsigned)gx0 < (unsigned)DW);
    const int off0 = v0 ? (gy0 * DW + gx0) : 0;

    const int i1 = tid + NTHREADS;
    const bool has1 = (i1 < SMH * SMW);
    const int ly1 = i1 / SMW, lx1 = i1 - ly1 * SMW;
    const int gy1 = blockIdx.y * TY + ly1 - 1;
    const int gx1 = blockIdx.x * TX + lx1 - 1;
    const bool v1 = has1 && ((unsigned)gy1 < (unsigned)DH) && ((unsigned)gx1 < (unsigned)DW);
    const int off1 = v1 ? (gy1 * DW + gx1) : 0;

    // incremental pointers for M/S halo loads
    const float* pM0 = Mp + (zbase - 1) * SLICE + off0;
    const float* pS0 = Sp + (zbase - 1) * SLICE + off0;
    const float* pM1 = Mp + (zbase - 1) * SLICE + off1;
    const float* pS1 = Sp + (zbase - 1) * SLICE + off1;

    // depth-2 M/S pipeline preload: slices zbase-1, zbase
    float Pm0, Ps0, Pm1, Ps1, Qm0, Qs0, Qm1, Qs1;
    {
        const bool zin = (zbase - 1 >= 0);
        Pm0 = (v0 && zin) ? __ldg(pM0) : 0.f;
        Ps0 = (v0 && zin) ? __ldg(pS0) : 0.f;
        Pm1 = (v1 && zin) ? __ldg(pM1) : 0.f;
        Ps1 = (v1 && zin) ? __ldg(pS1) : 0.f;
        pM0 += SLICE; pS0 += SLICE; pM1 += SLICE; pS1 += SLICE;
        Qm0 = v0 ? __ldg(pM0) : 0.f;
        Qs0 = v0 ? __ldg(pS0) : 0.f;
        Qm1 = v1 ? __ldg(pM1) : 0.f;
        Qs1 = v1 ? __ldg(pS1) : 0.f;
        pM0 += SLICE; pS0 += SLICE; pM1 += SLICE; pS1 += SLICE;
    }

    // depth-2 flow pipeline preload: z = zbase (emit j=2), zbase+1 (emit j=3)
    const float* pF = Fp + zbase * SLICE + y * DW + x;
    float Pfx = __ldg(pF), Pfy = __ldg(pF + NVOX), Pfz = __ldg(pF + 2 * NVOX);
    pF += SLICE;
    float Qfx = __ldg(pF), Qfy = __ldg(pF + NVOX), Qfz = __ldg(pF + 2 * NVOX);
    pF += SLICE;

    // per-slice separable responses, register ring of 3 (period matches unroll 3)
    float AM0, AM1, AM2, BM0, BM1, BM2, CM0, CM1, CM2, Mc1, Mc2;
    float AS0, AS1, AS2, BS0, BS1, BS2, CS0, CS1, CS2, Sc1, Sc2;
    AM0=AM1=BM0=BM1=CM0=CM1=Mc1=0.f;
    AS0=AS1=BS0=BS1=CS0=CS1=Sc1=0.f;
    float acc = 0.f;

    #pragma unroll 3
    for (int j = 0; j <= CZ + 1; ++j) {           // 18 iterations = 6 unroll groups
        const int b = j % 3;

        // commit slice (zbase-1+j) to smem
        sm[b][ly0][lx0] = make_float2(Pm0, Ps0);
        if (has1) sm[b][ly1][lx1] = make_float2(Pm1, Ps1);

        // rotate, issue loads for slice zbase+j+1 (consumed 2 iters later)
        Pm0 = Qm0; Ps0 = Qs0; Pm1 = Qm1; Ps1 = Qs1;
        if (j <= CZ - 1) {
            const bool zin = (zbase + j + 1 < DD);
            Qm0 = (v0 && zin) ? __ldg(pM0) : 0.f;
            Qs0 = (v0 && zin) ? __ldg(pS0) : 0.f;
            Qm1 = (v1 && zin) ? __ldg(pM1) : 0.f;
            Qs1 = (v1 && zin) ? __ldg(pS1) : 0.f;
            pM0 += SLICE; pS0 += SLICE; pM1 += SLICE; pS1 += SLICE;
        }
        __syncthreads();

        // in-plane separable responses (float2: M=.x, S=.y)
        const float2 a0 = sm[b][ty + 0][tx], a1 = sm[b][ty + 0][tx + 1], a2 = sm[b][ty + 0][tx + 2];
        const float2 q0 = sm[b][ty + 1][tx], q1 = sm[b][ty + 1][tx + 1], q2 = sm[b][ty + 1][tx + 2];
        const float2 c0 = sm[b][ty + 2][tx], c1 = sm[b][ty + 2][tx + 1], c2 = sm[b][ty + 2][tx + 2];

        {   // M
            const float rD0 = a2.x - a0.x, rSm0 = fmaf(2.f, a1.x, a0.x + a2.x), rB0 = a0.x + a1.x + a2.x;
            const float rD1 = q2.x - q0.x,                                      rB1 = q0.x + q1.x + q2.x;
            const float rD2 = c2.x - c0.x, rSm2 = fmaf(2.f, c1.x, c0.x + c2.x), rB2 = c0.x + c1.x + c2.x;
            AM2 = fmaf(2.f, rD1, rD0 + rD2);
            BM2 = rSm2 - rSm0;
            CM2 = fmaf(2.f, rB1, rB0 + rB2);
            Mc2 = q1.x;
        }
        {   // S
            const float rD0 = a2.y - a0.y, rSm0 = fmaf(2.f, a1.y, a0.y + a2.y), rB0 = a0.y + a1.y + a2.y;
            const float rD1 = q2.y - q0.y,                                      rB1 = q0.y + q1.y + q2.y;
            const float rD2 = c2.y - c0.y, rSm2 = fmaf(2.f, c1.y, c0.y + c2.y), rB2 = c0.y + c1.y + c2.y;
            AS2 = fmaf(2.f, rD1, rD0 + rD2);
            BS2 = rSm2 - rSm0;
            CS2 = fmaf(2.f, rB1, rB0 + rB2);
            Sc2 = q1.y;
        }

        // emit output voxel z = zbase + j - 2 once three slices are live
        if (j >= 2) {
            const float Mx = AM0 + AM1 + AM2;
            const float My = BM0 + BM1 + BM2;
            const float Mz = CM2 - CM0;
            const float Sx = AS0 + AS1 + AS2;
            const float Sy = BS0 + BS1 + BS2;
            const float Sz = CS2 - CS0;

            const float Id  = Mc1 - Sc1;
            const float Id2 = fmaf(Id, Id, FEPS);
            const float dS = fmaf(Sx, Sx, fmaf(Sy, Sy, fmaf(Sz, Sz, Id2)));
            const float dM = fmaf(Mx, Mx, fmaf(My, My, fmaf(Mz, Mz, Id2)));

            // Ux/(Uz+eps) == nx/nz up to measure-zero sets: Id and 1/(dS*dM) cancel
            const float nx = fmaf(Sx, dM, Mx * dS);
            const float ny = fmaf(Sy, dM, My * dS);
            const float nz = fmaf(Sz, dM, Mz * dS);
            const float rz = __fdividef(1.f, nz);
            const float dxz = fast_atanf(nx * rz);
            const float dyz = fast_atanf(ny * rz);

            const float ifz = __fdividef(1.f, Pfz + FEPS);
            const float fxz = fast_atanf(Pfx * ifz);
            const float fyz = fast_atanf(Pfy * ifz);

            const float e1 = fxz - dxz;
            const float e2 = fyz - dyz;
            acc = fmaf(e1, e1, acc);
            acc = fmaf(e2, e2, acc);

            // rotate flow pipeline; load F for z = zbase+j (emit at j+2)
            Pfx = Qfx; Pfy = Qfy; Pfz = Qfz;
            if (j <= CZ - 1) {
                Qfx = __ldg(pF);
                Qfy = __ldg(pF + NVOX);
                Qfz = __ldg(pF + 2 * NVOX);
                pF += SLICE;
            }
        }

        // ring shift — fully renamed away (ring period 3 == unroll period 3)
        AM0 = AM1; AM1 = AM2;  BM0 = BM1; BM1 = BM2;
        CM0 = CM1; CM1 = CM2;  Mc1 = Mc2;
        AS0 = AS1; AS1 = AS2;  BS0 = BS1; BS1 = BS2;
        CS0 = CS1; CS1 = CS2;  Sc1 = Sc2;
    }

    // block reduction: warp shuffle + smem
    #pragma unroll
    for (int o = 16; o > 0; o >>= 1) acc += __shfl_xor_sync(0xffffffffu, acc, o);
    if ((tid & 31) == 0) warpred[tid >> 5] = acc;
    __syncthreads();
    if (tid == 0) {
        float v = 0.f;
        #pragma unroll
        for (int w = 0; w < NTHREADS / 32; ++w) v += warpred[w];
        g_partial[bid] = v;
        __threadfence();
        const unsigned int c = atomicAdd(&g_count, 1u);
        isLast = (c == (unsigned)(NBLOCKS - 1));
    }
    __syncthreads();

    // last block reduces partials, writes scalar, resets counter
    if (isLast) {
        float s = 0.f;
        for (int i = tid; i < NBLOCKS; i += NTHREADS) s += g_partial[i];
        #pragma unroll
        for (int o = 16; o > 0; o >>= 1) s += __shfl_xor_sync(0xffffffffu, s, o);
        if ((tid & 31) == 0) warpred[tid >> 5] = s;
        __syncthreads();
        if (tid == 0) {
            float t = 0.f;
            #pragma unroll
            for (int w = 0; w < NTHREADS / 32; ++w) t += warpred[w];
            out[0] = t / (float)NVOX;
            g_count = 0u;
        }
    }
}

extern "C" void kernel_launch(void* const* d_in, const int* in_sizes, int n_in,
                              void* d_out, int out_size)
{
    const float* Mp = (const float*)d_in[0];
    const float* Sp = (const float*)d_in[1];
    const float* Fp = (const float*)d_in[2];
    float* out = (float*)d_out;

    dim3 grid(GXD, GYD, GZD);   // (5, 24, 10) = 1200 blocks
    dim3 block(TX, TY, 1);      // (32, 8)
    demons_kernel<<<grid, block>>>(Mp, Sp, Fp, out);
}

// round 9
// speedup vs baseline: 1.2053x; 1.1488x over previous
#include <cuda_runtime.h>
#include <math.h>

// dims: (1,1,D=160,H=192,W=160), x fastest
#define DW 160
#define DH 192
#define DD 160
#define SLICE (DH*DW)
#define NVOX (DD*SLICE)

#define TX 32
#define TY 8
#define CZ 16
#define SMW (TX+2)
#define SMH (TY+2)
#define NTHREADS (TX*TY)
#define GXD (DW/TX)   // 5
#define GYD (DH/TY)   // 24
#define GZD (DD/CZ)   // 10
#define NBLOCKS (GXD*GYD*GZD)   // 1200
#define FEPS 1e-10f

typedef unsigned long long u64;

// packed (lo,hi) f32x2 helpers — FFMA2/FADD2/FMUL2 only reachable via PTX
__device__ __forceinline__ u64 pk2(float lo, float hi) {
    u64 r; asm("mov.b64 %0, {%1, %2};" : "=l"(r) : "f"(lo), "f"(hi)); return r;
}
__device__ __forceinline__ void upk2(u64 v, float& lo, float& hi) {
    asm("mov.b64 {%0, %1}, %2;" : "=f"(lo), "=f"(hi) : "l"(v));
}
__device__ __forceinline__ u64 fma2(u64 a, u64 b, u64 c) {
    u64 d; asm("fma.rn.f32x2 %0, %1, %2, %3;" : "=l"(d) : "l"(a), "l"(b), "l"(c)); return d;
}
__device__ __forceinline__ u64 add2(u64 a, u64 b) {
    u64 d; asm("add.rn.f32x2 %0, %1, %2;" : "=l"(d) : "l"(a), "l"(b)); return d;
}
#define NEG1P 0xBF800000BF800000ULL   // (-1.f, -1.f)
#define TWOP  0x4000000040000000ULL   // ( 2.f,  2.f)

__device__ float g_partial[NBLOCKS];
__device__ unsigned int g_count = 0;

// minimax atan: odd poly on [0,1], reciprocal fold for |x|>1. max err ~2e-6 rad.
__device__ __forceinline__ float fast_atanf(float x)
{
    const float ax = fabsf(x);
    const bool inv = ax > 1.0f;
    const float t = inv ? __fdividef(1.0f, ax) : ax;
    const float z = t * t;
    float p = -0.0117212f;
    p = fmaf(p, z, 0.05265332f);
    p = fmaf(p, z, -0.11643287f);
    p = fmaf(p, z, 0.19354346f);
    p = fmaf(p, z, -0.33262347f);
    p = fmaf(p, z, 0.99997726f);
    p = p * t;
    const float r = inv ? (1.5707963267948966f - p) : p;
    return copysignf(r, x);
}

__global__ __launch_bounds__(NTHREADS, 4)
void demons_kernel(const float* __restrict__ Mp,
                   const float* __restrict__ Sp,
                   const float* __restrict__ Fp,
                   float* __restrict__ out)
{
    __shared__ u64 sm[2][SMH][SMW];         // packed (M,S) per cell, ping-pong
    __shared__ float warpred[NTHREADS / 32];
    __shared__ bool isLast;

    const int tx = threadIdx.x, ty = threadIdx.y;
    const int tid = ty * TX + tx;
    const int x = blockIdx.x * TX + tx;
    const int y = blockIdx.y * TY + ty;
    const int zbase = blockIdx.z * CZ;
    const int bid = blockIdx.x + GXD * (blockIdx.y + GYD * blockIdx.z);

    // halo mapping (z-invariant): each thread covers <=2 of 340 slots
    const int ly0 = tid / SMW, lx0 = tid - ly0 * SMW;
    const int gy0 = blockIdx.y * TY + ly0 - 1;
    const int gx0 = blockIdx.x * TX + lx0 - 1;
    const bool v0 = ((unsigned)gy0 < (unsigned)DH) && ((unsigned)gx0 < (unsigned)DW);
    const int off0 = v0 ? (gy0 * DW + gx0) : 0;

    const int i1 = tid + NTHREADS;
    const bool has1 = (i1 < SMH * SMW);
    const int ly1 = i1 / SMW, lx1 = i1 - ly1 * SMW;
    const int gy1 = blockIdx.y * TY + ly1 - 1;
    const int gx1 = blockIdx.x * TX + lx1 - 1;
    const bool v1 = has1 && ((unsigned)gy1 < (unsigned)DH) && ((unsigned)gx1 < (unsigned)DW);
    const int off1 = v1 ? (gy1 * DW + gx1) : 0;

    // incremental pointers for M/S halo loads
    const float* pM0 = Mp + (zbase - 1) * SLICE + off0;
    const float* pS0 = Sp + (zbase - 1) * SLICE + off0;
    const float* pM1 = Mp + (zbase - 1) * SLICE + off1;
    const float* pS1 = Sp + (zbase - 1) * SLICE + off1;

    // depth-2 M/S pipeline preload (packed pairs): slices zbase-1, zbase
    u64 P0, P1, Q0, Q1;
    {
        const bool zin = (zbase - 1 >= 0);
        const bool g0 = v0 && zin, g1 = v1 && zin;
        P0 = pk2(g0 ? __ldg(pM0) : 0.f, g0 ? __ldg(pS0) : 0.f);
        P1 = pk2(g1 ? __ldg(pM1) : 0.f, g1 ? __ldg(pS1) : 0.f);
        pM0 += SLICE; pS0 += SLICE; pM1 += SLICE; pS1 += SLICE;
        Q0 = pk2(v0 ? __ldg(pM0) : 0.f, v0 ? __ldg(pS0) : 0.f);
        Q1 = pk2(v1 ? __ldg(pM1) : 0.f, v1 ? __ldg(pS1) : 0.f);
        pM0 += SLICE; pS0 += SLICE; pM1 += SLICE; pS1 += SLICE;
    }

    const float* pF = Fp + zbase * SLICE + y * DW + x;

    // packed per-slice responses, register ring of 3
    u64 A0, A1, A2, B0, B1, B2, C0, C1, C2, c1r, c2r;
    A0 = A1 = B0 = B1 = C0 = C1 = c1r = 0ULL;
    float acc = 0.f;

    #pragma unroll 2
    for (int j = 0; j <= CZ + 1; ++j) {
        const int b = j & 1;

        // commit slice (zbase-1+j) to smem (packed)
        sm[b][ly0][lx0] = P0;
        if (has1) sm[b][ly1][lx1] = P1;

        // rotate, issue loads for slice zbase+j+1 (consumed 2 iters later)
        P0 = Q0; P1 = Q1;
        if (j <= CZ - 1) {
            const bool zin = (zbase + j + 1 < DD);
            const bool g0 = v0 && zin, g1 = v1 && zin;
            Q0 = pk2(g0 ? __ldg(pM0) : 0.f, g0 ? __ldg(pS0) : 0.f);
            Q1 = pk2(g1 ? __ldg(pM1) : 0.f, g1 ? __ldg(pS1) : 0.f);
            pM0 += SLICE; pS0 += SLICE; pM1 += SLICE; pS1 += SLICE;
        }
        __syncthreads();

        // in-plane separable responses, packed over (M,S)
        const u64 a0 = sm[b][ty + 0][tx], a1 = sm[b][ty + 0][tx + 1], a2 = sm[b][ty + 0][tx + 2];
        const u64 q0 = sm[b][ty + 1][tx], q1 = sm[b][ty + 1][tx + 1], q2 = sm[b][ty + 1][tx + 2];
        const u64 e0 = sm[b][ty + 2][tx], e1v = sm[b][ty + 2][tx + 1], e2v = sm[b][ty + 2][tx + 2];

        const u64 t0 = add2(a0, a2);
        const u64 rD0 = fma2(a0, NEG1P, a2);
        const u64 rS0 = fma2(TWOP, a1, t0);
        const u64 rB0 = add2(a1, t0);

        const u64 t1 = add2(q0, q2);
        const u64 rD1 = fma2(q0, NEG1P, q2);
        const u64 rB1 = add2(q1, t1);

        const u64 t2 = add2(e0, e2v);
        const u64 rD2 = fma2(e0, NEG1P, e2v);
        const u64 rS2 = fma2(TWOP, e1v, t2);
        const u64 rB2 = add2(e1v, t2);

        A2 = fma2(TWOP, rD1, add2(rD0, rD2));   // smooth_y x diff_x
        B2 = fma2(rS0, NEG1P, rS2);             // diff_y x smooth_x
        C2 = fma2(TWOP, rB1, add2(rB0, rB2));   // smooth_y x box_x
        c2r = q1;                               // center pair (M,S)

        // emit output voxel z = zbase + j - 2 once three slices are live
        if (j >= 2) {
            // flow loads first — covered by the math below
            const float fx = __ldg(pF);
            const float fy = __ldg(pF + NVOX);
            const float fz = __ldg(pF + 2 * NVOX);
            pF += SLICE;

            const u64 Gx = add2(add2(A0, A1), A2);     // (Mx, Sx)
            const u64 Gy = add2(add2(B0, B1), B2);     // (My, Sy)
            const u64 Gz = fma2(C0, NEG1P, C2);        // (Mz, Sz)

            float Mcv, Scv; upk2(c1r, Mcv, Scv);
            const float Id  = Mcv - Scv;
            const float Id2 = fmaf(Id, Id, FEPS);

            // d = (dM, dS) in one packed chain
            const u64 d = fma2(Gx, Gx, fma2(Gy, Gy, fma2(Gz, Gz, pk2(Id2, Id2))));

            float dM, dS; upk2(d, dM, dS);
            float Mx, Sx; upk2(Gx, Mx, Sx);
            float My, Sy; upk2(Gy, My, Sy);
            float Mz, Sz; upk2(Gz, Mz, Sz);

            // Ux/(Uz+eps) == nx/nz: Id and 1/(dS*dM) cancel
            const float nx = fmaf(Sx, dM, Mx * dS);
            const float ny = fmaf(Sy, dM, My * dS);
            const float nz = fmaf(Sz, dM, Mz * dS);
            const float rz = __fdividef(1.f, nz);
            const float dxz = fast_atanf(nx * rz);
            const float dyz = fast_atanf(ny * rz);

            const float ifz = __fdividef(1.f, fz + FEPS);
            const float fxz = fast_atanf(fx * ifz);
            const float fyz = fast_atanf(fy * ifz);

            const float d1 = fxz - dxz;
            const float d2 = fyz - dyz;
            acc = fmaf(d1, d1, acc);
            acc = fmaf(d2, d2, acc);
        }

        // ring shift (packed — half the MOV traffic of scalar)
        A0 = A1; A1 = A2;  B0 = B1; B1 = B2;
        C0 = C1; C1 = C2;  c1r = c2r;
    }

    // block reduction: warp shuffle + smem
    #pragma unroll
    for (int o = 16; o > 0; o >>= 1) acc += __shfl_xor_sync(0xffffffffu, acc, o);
    if ((tid & 31) == 0) warpred[tid >> 5] = acc;
    __syncthreads();
    if (tid == 0) {
        float v = 0.f;
        #pragma unroll
        for (int w = 0; w < NTHREADS / 32; ++w) v += warpred[w];
        g_partial[bid] = v;
        __threadfence();
        const unsigned int c = atomicAdd(&g_count, 1u);
        isLast = (c == (unsigned)(NBLOCKS - 1));
    }
    __syncthreads();

    // last block reduces partials, writes scalar, resets counter
    if (isLast) {
        float s = 0.f;
        for (int i = tid; i < NBLOCKS; i += NTHREADS) s += g_partial[i];
        #pragma unroll
        for (int o = 16; o > 0; o >>= 1) s += __shfl_xor_sync(0xffffffffu, s, o);
        if ((tid & 31) == 0) warpred[tid >> 5] = s;
        __syncthreads();
        if (tid == 0) {
            float t = 0.f;
            #pragma unroll
            for (int w = 0; w < NTHREADS / 32; ++w) t += warpred[w];
            out[0] = t / (float)NVOX;
            g_count = 0u;
        }
    }
}

extern "C" void kernel_launch(void* const* d_in, const int* in_sizes, int n_in,
                              void* d_out, int out_size)
{
    const float* Mp = (const float*)d_in[0];
    const float* Sp = (const float*)d_in[1];
    const float* Fp = (const float*)d_in[2];
    float* out = (float*)d_out;

    dim3 grid(GXD, GYD, GZD);   // (5, 24, 10) = 1200 blocks
    dim3 block(TX, TY, 1);      // (32, 8)
    demons_kernel<<<grid, block>>>(Mp, Sp, Fp, out);
}

// round 10
// speedup vs baseline: 1.3174x; 1.0930x over previous
#include <cuda_runtime.h>
#include <math.h>

// dims: (1,1,D=160,H=192,W=160), x fastest
#define DW 160
#define DH 192
#define DD 160
#define SLICE (DH*DW)
#define NVOX (DD*SLICE)

#define TX 32
#define TY 8
#define CZ 16
#define SMW (TX+2)
#define SMH (TY+2)
#define NTHREADS (TX*TY)
#define GXD (DW/TX)   // 5
#define GYD (DH/TY)   // 24
#define GZD (DD/CZ)   // 10
#define NBLOCKS (GXD*GYD*GZD)   // 1200
#define FEPS 1e-10f

#define NBUF 4
#define CELLS (SMH*SMW)
#define BUFBYTES (CELLS*8)

typedef unsigned long long u64;

// packed (lo,hi) f32x2 helpers — FFMA2/FADD2 only reachable via PTX
__device__ __forceinline__ u64 pk2(float lo, float hi) {
    u64 r; asm("mov.b64 %0, {%1, %2};" : "=l"(r) : "f"(lo), "f"(hi)); return r;
}
__device__ __forceinline__ void upk2(u64 v, float& lo, float& hi) {
    asm("mov.b64 {%0, %1}, %2;" : "=f"(lo), "=f"(hi) : "l"(v));
}
__device__ __forceinline__ u64 fma2(u64 a, u64 b, u64 c) {
    u64 d; asm("fma.rn.f32x2 %0, %1, %2, %3;" : "=l"(d) : "l"(a), "l"(b), "l"(c)); return d;
}
__device__ __forceinline__ u64 add2(u64 a, u64 b) {
    u64 d; asm("add.rn.f32x2 %0, %1, %2;" : "=l"(d) : "l"(a), "l"(b)); return d;
}
#define NEG1P 0xBF800000BF800000ULL   // (-1.f, -1.f)
#define TWOP  0x4000000040000000ULL   // ( 2.f,  2.f)

// 4-byte async copy global -> shared
__device__ __forceinline__ void cpa4(unsigned sdst, const float* gsrc) {
    asm volatile("cp.async.ca.shared.global [%0], [%1], 4;" :: "r"(sdst), "l"(gsrc));
}
#define CP_COMMIT() asm volatile("cp.async.commit_group;" ::: "memory")
#define CP_WAIT2()  asm volatile("cp.async.wait_group 2;" ::: "memory")

__device__ float g_partial[NBLOCKS];
__device__ unsigned int g_count = 0;
__device__ float g_zerosrc[8] = {0,0,0,0,0,0,0,0};

// minimax atan: odd poly on [0,1], reciprocal fold for |x|>1. max err ~2e-6 rad.
__device__ __forceinline__ float fast_atanf(float x)
{
    const float ax = fabsf(x);
    const bool inv = ax > 1.0f;
    const float t = inv ? __fdividef(1.0f, ax) : ax;
    const float z = t * t;
    float p = -0.0117212f;
    p = fmaf(p, z, 0.05265332f);
    p = fmaf(p, z, -0.11643287f);
    p = fmaf(p, z, 0.19354346f);
    p = fmaf(p, z, -0.33262347f);
    p = fmaf(p, z, 0.99997726f);
    p = p * t;
    const float r = inv ? (1.5707963267948966f - p) : p;
    return copysignf(r, x);
}

__global__ __launch_bounds__(NTHREADS, 4)
void demons_kernel(const float* __restrict__ Mp,
                   const float* __restrict__ Sp,
                   const float* __restrict__ Fp,
                   float* __restrict__ out)
{
    __shared__ u64 sm[NBUF][SMH][SMW];      // packed (M,S), 4-deep ring for cp.async
    __shared__ float warpred[NTHREADS / 32];
    __shared__ bool isLast;

    const int tx = threadIdx.x, ty = threadIdx.y;
    const int tid = ty * TX + tx;
    const int x = blockIdx.x * TX + tx;
    const int y = blockIdx.y * TY + ty;
    const int zbase = blockIdx.z * CZ;
    const int bid = blockIdx.x + GXD * (blockIdx.y + GYD * blockIdx.z);

    // halo mapping (z-invariant): each thread covers <=2 of 340 slots
    const int ly0 = tid / SMW, lx0 = tid - ly0 * SMW;
    const int gy0 = blockIdx.y * TY + ly0 - 1;
    const int gx0 = blockIdx.x * TX + lx0 - 1;
    const bool v0 = ((unsigned)gy0 < (unsigned)DH) && ((unsigned)gx0 < (unsigned)DW);
    const int off0 = v0 ? (gy0 * DW + gx0) : 0;

    const int i1 = tid + NTHREADS;
    const bool has1 = (i1 < SMH * SMW);
    const int ly1 = i1 / SMW, lx1 = i1 - ly1 * SMW;
    const int gy1 = blockIdx.y * TY + ly1 - 1;
    const int gx1 = blockIdx.x * TX + lx1 - 1;
    const bool v1 = has1 && ((unsigned)gy1 < (unsigned)DH) && ((unsigned)gx1 < (unsigned)DW);
    const int off1 = v1 ? (gy1 * DW + gx1) : 0;

    const unsigned sbase = (unsigned)__cvta_generic_to_shared(&sm[0][0][0]);
    const unsigned a0 = sbase + (unsigned)(ly0 * SMW + lx0) * 8u;
    const unsigned a1 = sbase + (unsigned)(ly1 * SMW + lx1) * 8u;
    const float* gz = g_zerosrc;

    // incremental pointers; start at slice zbase-1
    const float* pM0 = Mp + (zbase - 1) * SLICE + off0;
    const float* pS0 = Sp + (zbase - 1) * SLICE + off0;
    const float* pM1 = Mp + (zbase - 1) * SLICE + off1;
    const float* pS1 = Sp + (zbase - 1) * SLICE + off1;

    // prologue: 3 groups, slices zbase-1..zbase+1 into buffers 0..2
    #pragma unroll
    for (int k = 0; k < 3; ++k) {
        const bool zin = (zbase - 1 + k >= 0);
        const unsigned ab0 = a0 + (unsigned)k * BUFBYTES;
        cpa4(ab0,      (v0 && zin) ? pM0 : gz);
        cpa4(ab0 + 4u, (v0 && zin) ? pS0 : gz);
        if (has1) {
            const unsigned ab1 = a1 + (unsigned)k * BUFBYTES;
            cpa4(ab1,      (v1 && zin) ? pM1 : gz);
            cpa4(ab1 + 4u, (v1 && zin) ? pS1 : gz);
        }
        CP_COMMIT();
        pM0 += SLICE; pS0 += SLICE; pM1 += SLICE; pS1 += SLICE;
    }

    // flow register pipeline, depth 2 (z in [zbase, zbase+CZ-1], guard-free)
    const float* pF = Fp + zbase * SLICE + y * DW + x;
    float Pfx = __ldg(pF), Pfy = __ldg(pF + NVOX), Pfz = __ldg(pF + 2 * NVOX);
    pF += SLICE;
    float Qfx = __ldg(pF), Qfy = __ldg(pF + NVOX), Qfz = __ldg(pF + 2 * NVOX);
    pF += SLICE;

    // packed per-slice responses, register ring of 3
    u64 A0, A1, A2, B0, B1, B2, C0, C1, C2, c1r, c2r;
    A0 = A1 = B0 = B1 = C0 = C1 = c1r = 0ULL;
    float acc = 0.f;

    #pragma unroll 4
    for (int j = 0; j <= CZ + 1; ++j) {          // 18 iterations
        // group j (slice zbase-1+j) complete; barrier also releases buffer (j-1)&3
        CP_WAIT2();
        __syncthreads();

        // issue prefetch for slice zbase+2+j into buffer (j+3)&3; always commit
        if (j <= CZ - 2) {
            const bool zin = (zbase + 2 + j < DD);
            const unsigned ab0 = a0 + (unsigned)((j + 3) & 3) * BUFBYTES;
            cpa4(ab0,      (v0 && zin) ? pM0 : gz);
            cpa4(ab0 + 4u, (v0 && zin) ? pS0 : gz);
            if (has1) {
                const unsigned ab1 = a1 + (unsigned)((j + 3) & 3) * BUFBYTES;
                cpa4(ab1,      (v1 && zin) ? pM1 : gz);
                cpa4(ab1 + 4u, (v1 && zin) ? pS1 : gz);
            }
            pM0 += SLICE; pS0 += SLICE; pM1 += SLICE; pS1 += SLICE;
        }
        CP_COMMIT();

        const int b = j & 3;

        // in-plane separable responses, packed over (M,S)
        const u64 a0v = sm[b][ty + 0][tx], a1v = sm[b][ty + 0][tx + 1], a2v = sm[b][ty + 0][tx + 2];
        const u64 q0  = sm[b][ty + 1][tx], q1  = sm[b][ty + 1][tx + 1], q2  = sm[b][ty + 1][tx + 2];
        const u64 e0  = sm[b][ty + 2][tx], e1v = sm[b][ty + 2][tx + 1], e2v = sm[b][ty + 2][tx + 2];

        const u64 t0 = add2(a0v, a2v);
        const u64 rD0 = fma2(a0v, NEG1P, a2v);
        const u64 rS0 = fma2(TWOP, a1v, t0);
        const u64 rB0 = add2(a1v, t0);

        const u64 t1 = add2(q0, q2);
        const u64 rD1 = fma2(q0, NEG1P, q2);
        const u64 rB1 = add2(q1, t1);

        const u64 t2 = add2(e0, e2v);
        const u64 rD2 = fma2(e0, NEG1P, e2v);
        const u64 rS2 = fma2(TWOP, e1v, t2);
        const u64 rB2 = add2(e1v, t2);

        A2 = fma2(TWOP, rD1, add2(rD0, rD2));   // smooth_y x diff_x
        B2 = fma2(rS0, NEG1P, rS2);             // diff_y x smooth_x
        C2 = fma2(TWOP, rB1, add2(rB0, rB2));   // smooth_y x box_x
        c2r = q1;                               // center pair (M,S)

        // emit output voxel z = zbase + j - 2 once three slices are live
        if (j >= 2) {
            const u64 Gx = add2(add2(A0, A1), A2);     // (Mx, Sx)
            const u64 Gy = add2(add2(B0, B1), B2);     // (My, Sy)
            const u64 Gz = fma2(C0, NEG1P, C2);        // (Mz, Sz)

            float Mcv, Scv; upk2(c1r, Mcv, Scv);
            const float Id  = Mcv - Scv;
            const float Id2 = fmaf(Id, Id, FEPS);

            const u64 d = fma2(Gx, Gx, fma2(Gy, Gy, fma2(Gz, Gz, pk2(Id2, Id2))));

            float dM, dS; upk2(d, dM, dS);
            float Mx, Sx; upk2(Gx, Mx, Sx);
            float My, Sy; upk2(Gy, My, Sy);
            float Mz, Sz; upk2(Gz, Mz, Sz);

            // Ux/(Uz+eps) == nx/nz: Id and 1/(dS*dM) cancel
            const float nx = fmaf(Sx, dM, Mx * dS);
            const float ny = fmaf(Sy, dM, My * dS);
            const float nz = fmaf(Sz, dM, Mz * dS);
            const float rz = __fdividef(1.f, nz);
            const float dxz = fast_atanf(nx * rz);
            const float dyz = fast_atanf(ny * rz);

            const float ifz = __fdividef(1.f, Pfz + FEPS);
            const float fxz = fast_atanf(Pfx * ifz);
            const float fyz = fast_atanf(Pfy * ifz);

            const float d1 = fxz - dxz;
            const float d2 = fyz - dyz;
            acc = fmaf(d1, d1, acc);
            acc = fmaf(d2, d2, acc);

            // rotate flow pipeline; load F for z = zbase+j (used at j+2)
            Pfx = Qfx; Pfy = Qfy; Pfz = Qfz;
            if (j <= CZ - 1) {
                Qfx = __ldg(pF);
                Qfy = __ldg(pF + NVOX);
                Qfz = __ldg(pF + 2 * NVOX);
                pF += SLICE;
            }
        }

        // ring shift (packed)
        A0 = A1; A1 = A2;  B0 = B1; B1 = B2;
        C0 = C1; C1 = C2;  c1r = c2r;
    }

    // block reduction: warp shuffle + smem
    #pragma unroll
    for (int o = 16; o > 0; o >>= 1) acc += __shfl_xor_sync(0xffffffffu, acc, o);
    if ((tid & 31) == 0) warpred[tid >> 5] = acc;
    __syncthreads();
    if (tid == 0) {
        float v = 0.f;
        #pragma unroll
        for (int w = 0; w < NTHREADS / 32; ++w) v += warpred[w];
        g_partial[bid] = v;
        __threadfence();
        const unsigned int c = atomicAdd(&g_count, 1u);
        isLast = (c == (unsigned)(NBLOCKS - 1));
    }
    __syncthreads();

    // last block reduces partials, writes scalar, resets counter
    if (isLast) {
        float s = 0.f;
        for (int i = tid; i < NBLOCKS; i += NTHREADS) s += g_partial[i];
        #pragma unroll
        for (int o = 16; o > 0; o >>= 1) s += __shfl_xor_sync(0xffffffffu, s, o);
        if ((tid & 31) == 0) warpred[tid >> 5] = s;
        __syncthreads();
        if (tid == 0) {
            float t = 0.f;
            #pragma unroll
            for (int w = 0; w < NTHREADS / 32; ++w) t += warpred[w];
            out[0] = t / (float)NVOX;
            g_count = 0u;
        }
    }
}

extern "C" void kernel_launch(void* const* d_in, const int* in_sizes, int n_in,
                              void* d_out, int out_size)
{
    const float* Mp = (const float*)d_in[0];
    const float* Sp = (const float*)d_in[1];
    const float* Fp = (const float*)d_in[2];
    float* out = (float*)d_out;

    dim3 grid(GXD, GYD, GZD);   // (5, 24, 10) = 1200 blocks
    dim3 block(TX, TY, 1);      // (32, 8)
    demons_kernel<<<grid, block>>>(Mp, Sp, Fp, out);
}